// round 17
// baseline (speedup 1.0000x reference)
#include <cuda_runtime.h>
#include <math.h>

// Problem constants (fixed bench shapes)
#define BB    128
#define NN    1024
#define DIN   192
#define HH    128
#define KSLOT 3
#define NITER 3
#define EPSX  1e-5f
#define MTOT  (BB*NN)              // 131072 token rows
#define SCALE 0.08838834764831845f // 1/sqrt(128)

#define SPLIT  8                   // stream CTAs per batch element
#define TPS    (NN/SPLIT)          // 128 tokens per split
#define TSTR   132                 // padded tile row stride (floats)

typedef unsigned int uint32;
typedef unsigned long long ull;

// ---------------------------------------------------------------------------
// Scratch (device globals: allocation-free rule)
// ---------------------------------------------------------------------------
__device__ float g_WpT[DIN*HH];
__device__ float g_inputs[(size_t)MTOT*HH];  // 67 MB
__device__ float g_slots[BB*KSLOT*HH];
__device__ float g_qp[BB*KSLOT*HH];          // per-iter q' = q@Wk (scaled)
__device__ float g_qbk[BB*KSLOT];            // per-iter q·bk
__device__ float g_upart[BB*SPLIT*KSLOT*HH]; // 1.5 MB split partials
__device__ float g_wpart[BB*SPLIT*KSLOT];

// f32x2 helpers (gemm) ------------------------------------------------------
__device__ __forceinline__ ull splat2(float a) {
    ull r; asm("mov.b64 %0, {%1, %1};" : "=l"(r) : "f"(a)); return r;
}
__device__ __forceinline__ void fma2(ull& d, ull a, ull b) {
    asm("fma.rn.f32x2 %0, %1, %2, %0;" : "+l"(d) : "l"(a), "l"(b));
}
__device__ __forceinline__ float2 unpack2(ull v) {
    float2 r; asm("mov.b64 {%0, %1}, %2;" : "=f"(r.x), "=f"(r.y) : "l"(v)); return r;
}

// ---------------------------------------------------------------------------
// Prep: transpose Wp; init slots
// ---------------------------------------------------------------------------
__global__ void prep_kernel(const float* __restrict__ Wp,
                            const float* __restrict__ noise,
                            const float* __restrict__ slot_mu,
                            const float* __restrict__ slot_lsig)
{
    int i = blockIdx.x * blockDim.x + threadIdx.x;
    if (i < HH*DIN) {
        int r = i / DIN, c = i % DIN;
        g_WpT[c*HH + r] = Wp[i];
    }
    if (i < BB*KSLOT*HH) {
        int kh = i % (KSLOT*HH);
        g_slots[i] = slot_mu[kh] + expf(slot_lsig[kh]) * noise[i];
    }
}

// ---------------------------------------------------------------------------
// SGEMM (R8, proven): double-buffered smem, f32x2 FMA, LayerNorm epilogue.
// ---------------------------------------------------------------------------
template<int KDIM>
__global__ void __launch_bounds__(256)
gemm_ln(const float* __restrict__ A, const float* __restrict__ Bm,
        const float* __restrict__ bias, const float* __restrict__ gamma,
        const float* __restrict__ beta, float* __restrict__ out)
{
    __shared__ __align__(16) float As[2][8][132];
    __shared__ __align__(16) float Bs[2][8][128];
    __shared__ float psum[16][129];
    __shared__ float psq [16][129];
    __shared__ float smu[128], srs[128];

    const int tid = threadIdx.x;
    const int tx = tid & 15, ty = tid >> 4;
    const int m0 = blockIdx.x * 128;

    const int aRow = tid >> 1;
    const int aCol = (tid & 1) * 4;
    const int bRow = tid >> 5;
    const int bCol = (tid & 31) * 4;

    const float* Ab = A + (size_t)m0 * KDIM;
    const int NT = KDIM / 8;

    ull acc2[8][4];
    #pragma unroll
    for (int i = 0; i < 8; i++)
        #pragma unroll
        for (int j = 0; j < 4; j++) acc2[i][j] = 0ull;

    {
        float4 a4 = *(const float4*)(Ab + (size_t)aRow * KDIM + aCol);
        As[0][aCol+0][aRow] = a4.x;
        As[0][aCol+1][aRow] = a4.y;
        As[0][aCol+2][aRow] = a4.z;
        As[0][aCol+3][aRow] = a4.w;
        *(float4*)&Bs[0][bRow][bCol] =
            *(const float4*)(Bm + (size_t)bRow * HH + bCol);
    }
    __syncthreads();

    for (int t = 0; t < NT; t++) {
        const int buf = t & 1;
        float4 na, nb;
        if (t + 1 < NT) {
            na = *(const float4*)(Ab + (size_t)aRow * KDIM + ((t+1)*8 + aCol));
            nb = *(const float4*)(Bm + (size_t)((t+1)*8 + bRow) * HH + bCol);
        }
        #pragma unroll
        for (int kk = 0; kk < 8; kk++) {
            float a[8];
            *(float4*)&a[0] = *(const float4*)&As[buf][kk][ty*8];
            *(float4*)&a[4] = *(const float4*)&As[buf][kk][ty*8+4];
            ull b2[4];
            const ull* bp = (const ull*)&Bs[buf][kk][tx*8];
            b2[0] = bp[0]; b2[1] = bp[1]; b2[2] = bp[2]; b2[3] = bp[3];
            #pragma unroll
            for (int i = 0; i < 8; i++) {
                ull av = splat2(a[i]);
                fma2(acc2[i][0], av, b2[0]);
                fma2(acc2[i][1], av, b2[1]);
                fma2(acc2[i][2], av, b2[2]);
                fma2(acc2[i][3], av, b2[3]);
            }
        }
        if (t + 1 < NT) {
            const int nbuf = buf ^ 1;
            As[nbuf][aCol+0][aRow] = na.x;
            As[nbuf][aCol+1][aRow] = na.y;
            As[nbuf][aCol+2][aRow] = na.z;
            As[nbuf][aCol+3][aRow] = na.w;
            *(float4*)&Bs[nbuf][bRow][bCol] = nb;
            __syncthreads();
        }
    }

    float accf[8][8];
    float bj[8];
    #pragma unroll
    for (int j = 0; j < 8; j++) bj[j] = bias[tx*8 + j];
    #pragma unroll
    for (int i = 0; i < 8; i++)
        #pragma unroll
        for (int jp = 0; jp < 4; jp++) {
            float2 f = unpack2(acc2[i][jp]);
            accf[i][2*jp]   = f.x + bj[2*jp];
            accf[i][2*jp+1] = f.y + bj[2*jp+1];
        }

    __syncthreads();
    #pragma unroll
    for (int i = 0; i < 8; i++) {
        int row = ty*8 + i;
        float s = 0.f, q = 0.f;
        #pragma unroll
        for (int j = 0; j < 8; j++) { s += accf[i][j]; q += accf[i][j]*accf[i][j]; }
        psum[tx][row] = s;
        psq [tx][row] = q;
    }
    __syncthreads();
    if (tid < 128) {
        float s = 0.f, q = 0.f;
        #pragma unroll
        for (int t = 0; t < 16; t++) { s += psum[t][tid]; q += psq[t][tid]; }
        float mu  = s * (1.f/128.f);
        float var = q * (1.f/128.f) - mu*mu;
        smu[tid] = mu;
        srs[tid] = rsqrtf(var + EPSX);
    }
    __syncthreads();
    float gj[8], b2j[8];
    #pragma unroll
    for (int j = 0; j < 8; j++) { gj[j] = gamma[tx*8+j]; b2j[j] = beta[tx*8+j]; }
    #pragma unroll
    for (int i = 0; i < 8; i++) {
        int row = ty*8 + i;
        float mu = smu[row], rs = srs[row];
        float o[8];
        #pragma unroll
        for (int j = 0; j < 8; j++) o[j] = (accf[i][j]-mu)*rs*gj[j] + b2j[j];
        float4* dst = (float4*)(out + (size_t)(m0+row)*HH + tx*8);
        dst[0] = make_float4(o[0], o[1], o[2], o[3]);
        dst[1] = make_float4(o[4], o[5], o[6], o[7]);
    }
}

// ---------------------------------------------------------------------------
// Shared helpers for the iteration kernels
// ---------------------------------------------------------------------------
__device__ __forceinline__ float geluf(float x) {
    return 0.5f * x * (1.f + erff(x * 0.70710678118654752f));
}

__device__ __forceinline__ void warp_ln_row(const float* __restrict__ src,
                                            float* __restrict__ dst,
                                            const float* __restrict__ gamma,
                                            const float* __restrict__ beta,
                                            int lane)
{
    float4 xv = *(const float4*)(src + lane*4);
    float s = xv.x + xv.y + xv.z + xv.w;
    #pragma unroll
    for (int off = 16; off > 0; off >>= 1) s += __shfl_xor_sync(0xffffffffu, s, off);
    float mu = s * (1.f/128.f);
    float d0 = xv.x-mu, d1 = xv.y-mu, d2 = xv.z-mu, d3 = xv.w-mu;
    float q = d0*d0 + d1*d1 + d2*d2 + d3*d3;
    #pragma unroll
    for (int off = 16; off > 0; off >>= 1) q += __shfl_xor_sync(0xffffffffu, q, off);
    float rs = rsqrtf(q * (1.f/128.f) + EPSX);
    float4 g4 = *(const float4*)(gamma + lane*4);
    float4 b4 = *(const float4*)(beta  + lane*4);
    float4 o;
    o.x = d0*rs*g4.x + b4.x;
    o.y = d1*rs*g4.y + b4.y;
    o.z = d2*rs*g4.z + b4.z;
    o.w = d3*rs*g4.w + b4.w;
    *(float4*)(dst + lane*4) = o;
}

// From final slots (s_fin, smem) compute q'=q@Wk (scaled) + qbk, write global.
// Must be called by ALL threads of a 384-thread block.
__device__ void qp_tail(const float (*s_fin)[HH], float (*s_ln)[HH],
                        float (*q_s)[HH],
                        const float* __restrict__ gs, const float* __restrict__ bs,
                        const float* __restrict__ Wq, const float* __restrict__ bq,
                        const float* __restrict__ Wk, const float* __restrict__ bk,
                        int b, int tid, int lane, int warp)
{
    if (warp < KSLOT) warp_ln_row(s_fin[warp], s_ln[warp], gs, bs, lane);
    __syncthreads();
    if (tid < HH) {
        const int j = tid;
        const float4* wr = (const float4*)(Wq + (size_t)j*HH);
        float d0 = 0.f, d1 = 0.f, d2 = 0.f;
        #pragma unroll 8
        for (int i = 0; i < HH/4; i++) {
            float4 w  = wr[i];
            float4 a0 = *(const float4*)&s_ln[0][i*4];
            float4 a1 = *(const float4*)&s_ln[1][i*4];
            float4 a2 = *(const float4*)&s_ln[2][i*4];
            d0 += w.x*a0.x + w.y*a0.y + w.z*a0.z + w.w*a0.w;
            d1 += w.x*a1.x + w.y*a1.y + w.z*a1.z + w.w*a1.w;
            d2 += w.x*a2.x + w.y*a2.y + w.z*a2.z + w.w*a2.w;
        }
        float bb = bq[j];
        q_s[0][j] = (d0 + bb) * SCALE;
        q_s[1][j] = (d1 + bb) * SCALE;
        q_s[2][j] = (d2 + bb) * SCALE;
    }
    __syncthreads();
    if (tid < KSLOT*HH) {
        const int s = tid >> 7, i = tid & 127;
        float acc = 0.f;
        #pragma unroll 8
        for (int j = 0; j < HH; j++)
            acc = fmaf(q_s[s][j], Wk[j*HH + i], acc);
        g_qp[b*KSLOT*HH + tid] = acc;
    }
    if (tid < KSLOT) {
        const int s = tid;
        float acc = 0.f;
        const float4* bk4 = (const float4*)bk;
        #pragma unroll 8
        for (int i = 0; i < HH/4; i++) {
            float4 bv4 = bk4[i];
            float4 qv  = *(const float4*)&q_s[s][i*4];
            acc += qv.x*bv4.x + qv.y*bv4.y + qv.z*bv4.z + qv.w*bv4.w;
        }
        g_qbk[b*KSLOT + s] = acc;
    }
}

// ---------------------------------------------------------------------------
// qp0: q' for iteration 0 (from initial slots)
// ---------------------------------------------------------------------------
__global__ void __launch_bounds__(384)
qp0_kernel(const float* __restrict__ Wq, const float* __restrict__ bq,
           const float* __restrict__ Wk, const float* __restrict__ bk,
           const float* __restrict__ gs, const float* __restrict__ bs)
{
    __shared__ __align__(16) float s_fin[KSLOT][HH];
    __shared__ __align__(16) float s_ln [KSLOT][HH];
    __shared__ __align__(16) float q_s  [KSLOT][HH];
    const int b = blockIdx.x;
    const int tid = threadIdx.x, lane = tid & 31, warp = tid >> 5;
    s_fin[0][tid] = g_slots[b*KSLOT*HH + tid];
    __syncthreads();
    qp_tail(s_fin, s_ln, q_s, gs, bs, Wq, bq, Wk, bk, b, tid, lane, warp);
}

// ---------------------------------------------------------------------------
// stream_kernel: grid (SPLIT, BB), 256 threads. Each CTA streams 128 tokens:
// smem tile (plain LDG.128), thread-per-token dots + softmax (no shuffles),
// warp-per-token partial u' accumulation, partials to global.
// ---------------------------------------------------------------------------
struct StreamSmem {
    float tile[TPS][TSTR];       // 67584 B
    float qp[KSLOT][HH];
    float w [KSLOT][TPS];
    float upart[8][KSLOT][HH];   // per-warp partials
    float wpart[8][KSLOT];
    float qbk[KSLOT];
};

__global__ void __launch_bounds__(256)
stream_kernel(float* __restrict__ out_attn, int writeAttn)
{
    extern __shared__ __align__(16) char sm_raw[];
    StreamSmem& S = *reinterpret_cast<StreamSmem*>(sm_raw);

    const int sp  = blockIdx.x;
    const int b   = blockIdx.y;
    const int tid = threadIdx.x;
    const int lane = tid & 31;
    const int warp = tid >> 5;

    // qp / qbk (small, L2-hot)
    #pragma unroll
    for (int i = tid; i < KSLOT*HH; i += 256)
        S.qp[0][i] = g_qp[b*KSLOT*HH + i];
    if (tid < KSLOT) S.qbk[tid] = g_qbk[b*KSLOT + tid];

    // tile load: 16 independent float4 per thread
    {
        const float4* src = (const float4*)(g_inputs +
                             ((size_t)b*NN + (size_t)sp*TPS) * HH);
        #pragma unroll
        for (int k = 0; k < 16; k++) {
            int i = tid + k*256;
            int tok = i >> 5, c4 = i & 31;
            *(float4*)&S.tile[tok][c4*4] = src[i];
        }
    }
    __syncthreads();

    // dots + softmax: thread-per-token
    if (tid < TPS) {
        const float* row = &S.tile[tid][0];
        float d0 = S.qbk[0], d1 = S.qbk[1], d2 = S.qbk[2];
        #pragma unroll 8
        for (int i = 0; i < HH/4; i++) {
            float4 x  = *(const float4*)(row + i*4);
            float4 p0 = *(const float4*)&S.qp[0][i*4];
            float4 p1 = *(const float4*)&S.qp[1][i*4];
            float4 p2 = *(const float4*)&S.qp[2][i*4];
            d0 += p0.x*x.x + p0.y*x.y + p0.z*x.z + p0.w*x.w;
            d1 += p1.x*x.x + p1.y*x.y + p1.z*x.z + p1.w*x.w;
            d2 += p2.x*x.x + p2.y*x.y + p2.z*x.z + p2.w*x.w;
        }
        float mx = fmaxf(d0, fmaxf(d1, d2));
        float e0 = expf(d0-mx), e1 = expf(d1-mx), e2 = expf(d2-mx);
        float inv = 1.f / (e0 + e1 + e2);
        float w0 = e0*inv, w1 = e1*inv, w2 = e2*inv;
        S.w[0][tid] = w0;
        S.w[1][tid] = w1;
        S.w[2][tid] = w2;
        if (writeAttn) {
            float* ob = out_attn + (size_t)b*KSLOT*NN + sp*TPS + tid;
            ob[0]    = w0;
            ob[NN]   = w1;
            ob[2*NN] = w2;
        }
    }
    __syncthreads();

    // partial u' accumulation: warp-per-token, 16 tokens per warp
    {
        float4 ac0 = make_float4(0,0,0,0);
        float4 ac1 = make_float4(0,0,0,0);
        float4 ac2 = make_float4(0,0,0,0);
        float ws0 = 0.f, ws1 = 0.f, ws2 = 0.f;
        #pragma unroll
        for (int j = 0; j < TPS/8; j++) {
            int n = warp + 8*j;
            float w0 = S.w[0][n], w1 = S.w[1][n], w2 = S.w[2][n];
            float4 x = *(const float4*)&S.tile[n][lane*4];
            ac0.x = fmaf(w0, x.x, ac0.x); ac0.y = fmaf(w0, x.y, ac0.y);
            ac0.z = fmaf(w0, x.z, ac0.z); ac0.w = fmaf(w0, x.w, ac0.w);
            ac1.x = fmaf(w1, x.x, ac1.x); ac1.y = fmaf(w1, x.y, ac1.y);
            ac1.z = fmaf(w1, x.z, ac1.z); ac1.w = fmaf(w1, x.w, ac1.w);
            ac2.x = fmaf(w2, x.x, ac2.x); ac2.y = fmaf(w2, x.y, ac2.y);
            ac2.z = fmaf(w2, x.z, ac2.z); ac2.w = fmaf(w2, x.w, ac2.w);
            ws0 += w0; ws1 += w1; ws2 += w2;
        }
        *(float4*)&S.upart[warp][0][lane*4] = ac0;
        *(float4*)&S.upart[warp][1][lane*4] = ac1;
        *(float4*)&S.upart[warp][2][lane*4] = ac2;
        if (lane == 0) {
            S.wpart[warp][0] = ws0;
            S.wpart[warp][1] = ws1;
            S.wpart[warp][2] = ws2;
        }
    }
    __syncthreads();

    // fold 8 warps, write CTA partials (coalesced)
    if (tid < KSLOT*HH) {
        const int s = (tid >> 7), i = tid & 127;
        float a = 0.f;
        #pragma unroll
        for (int w = 0; w < 8; w++) a += S.upart[w][s][i];
        g_upart[((size_t)(b*SPLIT + sp)*KSLOT + s)*HH + i] = a;
        if (i < 256 - KSLOT*HH) {} // keep 256-thread blocks busy-free (no-op)
    }
    // (with 256 threads, tid<384 clips: handle remaining 128 entries)
    {
        int t2 = tid + 256;
        if (t2 < KSLOT*HH) {
            const int s = (t2 >> 7), i = t2 & 127;
            float a = 0.f;
            #pragma unroll
            for (int w = 0; w < 8; w++) a += S.upart[w][s][i];
            g_upart[((size_t)(b*SPLIT + sp)*KSLOT + s)*HH + i] = a;
        }
    }
    if (tid < KSLOT) {
        float a = 0.f;
        #pragma unroll
        for (int w = 0; w < 8; w++) a += S.wpart[w][tid];
        g_wpart[(b*SPLIT + sp)*KSLOT + tid] = a;
    }
}

// ---------------------------------------------------------------------------
// reduce_kernel: grid BB, 384 threads. Fold split partials, GRU + MLP,
// write slots, compute next iteration's qp.
// ---------------------------------------------------------------------------
__global__ void __launch_bounds__(384)
reduce_kernel(const float* __restrict__ Wq,  const float* __restrict__ bq,
              const float* __restrict__ Wk,  const float* __restrict__ bk,
              const float* __restrict__ Wv,  const float* __restrict__ bv,
              const float* __restrict__ gs,  const float* __restrict__ bs,
              const float* __restrict__ Wih, const float* __restrict__ bih,
              const float* __restrict__ Whh, const float* __restrict__ bhh,
              const float* __restrict__ W1,  const float* __restrict__ b1,
              const float* __restrict__ W2,  const float* __restrict__ b2,
              const float* __restrict__ gm,  const float* __restrict__ bm,
              float* __restrict__ out_slots, int writeSlots, int computeQp)
{
    __shared__ __align__(16) float upr  [KSLOT][HH];
    __shared__ __align__(16) float u_s  [KSLOT][HH];
    __shared__ __align__(16) float s_prev[KSLOT][HH];
    __shared__ __align__(16) float s_new[KSLOT][HH];
    __shared__ __align__(16) float m_ln [KSLOT][HH];
    __shared__ __align__(16) float s_fin[KSLOT][HH];
    __shared__ __align__(16) float s_ln2[KSLOT][HH];
    __shared__ __align__(16) float q_s2 [KSLOT][HH];
    __shared__ __align__(16) float gi[KSLOT][3*HH];
    __shared__ __align__(16) float gh[KSLOT][3*HH];
    __shared__ __align__(16) float h1[KSLOT][2*HH];
    __shared__ float wsr[KSLOT];

    const int b   = blockIdx.x;
    const int tid = threadIdx.x;
    const int lane = tid & 31;
    const int warp = tid >> 5;

    s_prev[0][tid] = g_slots[b*KSLOT*HH + tid];

    // fold split partials
    {
        const int s = tid >> 7, i = tid & 127;
        float a = 0.f;
        #pragma unroll
        for (int sp = 0; sp < SPLIT; sp++)
            a += g_upart[((size_t)(b*SPLIT + sp)*KSLOT + s)*HH + i];
        upr[s][i] = a;
    }
    if (tid < KSLOT) {
        float a = 0.f;
        #pragma unroll
        for (int sp = 0; sp < SPLIT; sp++)
            a += g_wpart[(b*SPLIT + sp)*KSLOT + tid];
        wsr[tid] = a;
    }
    __syncthreads();

    // updates = u' @ Wv^T + W·bv
    {
        const int s = tid >> 7, j = tid & 127;
        const float4* wr = (const float4*)(Wv + (size_t)j*HH);
        float acc = 0.f;
        #pragma unroll 8
        for (int i = 0; i < HH/4; i++) {
            float4 w = wr[i];
            float4 x = *(const float4*)&upr[s][i*4];
            acc += w.x*x.x + w.y*x.y + w.z*x.z + w.w*x.w;
        }
        u_s[s][j] = acc + wsr[s] * bv[j];
    }
    __syncthreads();

    // GRU gates
    {
        const int o = tid;
        {
            const float4* wr = (const float4*)(Wih + (size_t)o*HH);
            float d0=0,d1=0,d2=0;
            #pragma unroll 4
            for (int i = 0; i < HH/4; i++) {
                float4 w  = wr[i];
                float4 x0 = *(const float4*)&u_s[0][i*4];
                float4 x1 = *(const float4*)&u_s[1][i*4];
                float4 x2 = *(const float4*)&u_s[2][i*4];
                d0 += w.x*x0.x + w.y*x0.y + w.z*x0.z + w.w*x0.w;
                d1 += w.x*x1.x + w.y*x1.y + w.z*x1.z + w.w*x1.w;
                d2 += w.x*x2.x + w.y*x2.y + w.z*x2.z + w.w*x2.w;
            }
            float bb = bih[o];
            gi[0][o] = d0+bb; gi[1][o] = d1+bb; gi[2][o] = d2+bb;
        }
        {
            const float4* wr = (const float4*)(Whh + (size_t)o*HH);
            float d0=0,d1=0,d2=0;
            #pragma unroll 4
            for (int i = 0; i < HH/4; i++) {
                float4 w  = wr[i];
                float4 x0 = *(const float4*)&s_prev[0][i*4];
                float4 x1 = *(const float4*)&s_prev[1][i*4];
                float4 x2 = *(const float4*)&s_prev[2][i*4];
                d0 += w.x*x0.x + w.y*x0.y + w.z*x0.z + w.w*x0.w;
                d1 += w.x*x1.x + w.y*x1.y + w.z*x1.z + w.w*x1.w;
                d2 += w.x*x2.x + w.y*x2.y + w.z*x2.z + w.w*x2.w;
            }
            float bb = bhh[o];
            gh[0][o] = d0+bb; gh[1][o] = d1+bb; gh[2][o] = d2+bb;
        }
    }
    __syncthreads();
    {
        int s = tid >> 7, j = tid & 127;
        float ir = gi[s][j], iz = gi[s][HH+j], inn = gi[s][2*HH+j];
        float hr = gh[s][j], hz = gh[s][HH+j], hn  = gh[s][2*HH+j];
        float r  = 1.f / (1.f + expf(-(ir+hr)));
        float z  = 1.f / (1.f + expf(-(iz+hz)));
        float nn = tanhf(inn + r*hn);
        s_new[s][j] = (1.f - z)*nn + z*s_prev[s][j];
    }
    __syncthreads();

    // MLP with residual
    if (warp < KSLOT) warp_ln_row(s_new[warp], m_ln[warp], gm, bm, lane);
    __syncthreads();
    if (tid < 2*HH) {
        const int jr = tid;
        const float4* wr = (const float4*)(W1 + (size_t)jr*HH);
        float d0=0,d1=0,d2=0;
        #pragma unroll 4
        for (int i = 0; i < HH/4; i++) {
            float4 w  = wr[i];
            float4 x0 = *(const float4*)&m_ln[0][i*4];
            float4 x1 = *(const float4*)&m_ln[1][i*4];
            float4 x2 = *(const float4*)&m_ln[2][i*4];
            d0 += w.x*x0.x + w.y*x0.y + w.z*x0.z + w.w*x0.w;
            d1 += w.x*x1.x + w.y*x1.y + w.z*x1.z + w.w*x1.w;
            d2 += w.x*x2.x + w.y*x2.y + w.z*x2.z + w.w*x2.w;
        }
        float bb = b1[jr];
        h1[0][jr] = geluf(d0+bb);
        h1[1][jr] = geluf(d1+bb);
        h1[2][jr] = geluf(d2+bb);
    }
    __syncthreads();
    if (tid < HH) {
        const int j = tid;
        const float4* wr = (const float4*)(W2 + (size_t)j*2*HH);
        float d0=0,d1=0,d2=0;
        #pragma unroll 4
        for (int i = 0; i < (2*HH)/4; i++) {
            float4 w  = wr[i];
            float4 x0 = *(const float4*)&h1[0][i*4];
            float4 x1 = *(const float4*)&h1[1][i*4];
            float4 x2 = *(const float4*)&h1[2][i*4];
            d0 += w.x*x0.x + w.y*x0.y + w.z*x0.z + w.w*x0.w;
            d1 += w.x*x1.x + w.y*x1.y + w.z*x1.z + w.w*x1.w;
            d2 += w.x*x2.x + w.y*x2.y + w.z*x2.z + w.w*x2.w;
        }
        float bb = b2[j];
        float f0 = s_new[0][j] + d0 + bb;
        float f1 = s_new[1][j] + d1 + bb;
        float f2 = s_new[2][j] + d2 + bb;
        s_fin[0][j] = f0;
        s_fin[1][j] = f1;
        s_fin[2][j] = f2;
        g_slots[b*KSLOT*HH + 0*HH + j] = f0;
        g_slots[b*KSLOT*HH + 1*HH + j] = f1;
        g_slots[b*KSLOT*HH + 2*HH + j] = f2;
        if (writeSlots) {
            out_slots[(size_t)b*KSLOT*HH + 0*HH + j] = f0;
            out_slots[(size_t)b*KSLOT*HH + 1*HH + j] = f1;
            out_slots[(size_t)b*KSLOT*HH + 2*HH + j] = f2;
        }
    }
    __syncthreads();

    if (computeQp)
        qp_tail(s_fin, s_ln2, q_s2, gs, bs, Wq, bq, Wk, bk, b, tid, lane, warp);
}

// ---------------------------------------------------------------------------
// Launch
// ---------------------------------------------------------------------------
extern "C" void kernel_launch(void* const* d_in, const int* in_sizes, int n_in,
                              void* d_out, int out_size)
{
    const float* patch = (const float*)d_in[0];
    const float* noise = (const float*)d_in[1];
    const float* smu   = (const float*)d_in[2];
    const float* slsig = (const float*)d_in[3];
    const float* Wp    = (const float*)d_in[4];
    const float* bp    = (const float*)d_in[5];
    const float* g_in  = (const float*)d_in[6];
    const float* b_in  = (const float*)d_in[7];
    const float* Wq    = (const float*)d_in[8];
    const float* bq    = (const float*)d_in[9];
    const float* Wk    = (const float*)d_in[10];
    const float* bk    = (const float*)d_in[11];
    const float* Wv    = (const float*)d_in[12];
    const float* bv    = (const float*)d_in[13];
    const float* Wih   = (const float*)d_in[14];
    const float* bih   = (const float*)d_in[15];
    const float* Whh   = (const float*)d_in[16];
    const float* bhh   = (const float*)d_in[17];
    const float* gs    = (const float*)d_in[18];
    const float* bs    = (const float*)d_in[19];
    const float* W1    = (const float*)d_in[20];
    const float* b1    = (const float*)d_in[21];
    const float* W2    = (const float*)d_in[22];
    const float* b2    = (const float*)d_in[23];
    const float* gm    = (const float*)d_in[24];
    const float* bm    = (const float*)d_in[25];

    float *pWpT, *pIn;
    cudaGetSymbolAddress((void**)&pWpT, g_WpT);
    cudaGetSymbolAddress((void**)&pIn,  g_inputs);

    const int slotsElems = BB*KSLOT*HH;
    const int attnElems  = BB*KSLOT*NN;
    const int writeSlots = (out_size >= slotsElems) ? 1 : 0;
    const int writeAttn  = (out_size >= slotsElems + attnElems) ? 1 : 0;
    float* outSlots = (float*)d_out;
    float* outAttn  = (float*)d_out + slotsElems;

    const int streamSmem = (int)sizeof(StreamSmem);
    static int attrSet = 0;
    if (!attrSet) {
        cudaFuncSetAttribute(stream_kernel,
                             cudaFuncAttributeMaxDynamicSharedMemorySize, streamSmem);
        attrSet = 1;
    }

    // 1) transpose Wp + init slots; qp for iteration 0
    prep_kernel<<<192, 256>>>(Wp, noise, smu, slsig);
    qp0_kernel<<<BB, 384>>>(Wq, bq, Wk, bk, gs, bs);

    // 2) inputs = LN(X @ Wp^T + bp)
    gemm_ln<DIN><<<MTOT/128, 256>>>(patch, pWpT, bp, g_in, b_in, pIn);

    // 3) 3 slot-attention iterations: wide stream + narrow reduce
    for (int it = 0; it < NITER; it++) {
        int last = (it == NITER - 1);
        dim3 sgrid(SPLIT, BB);
        stream_kernel<<<sgrid, 256, streamSmem>>>(outAttn, last ? writeAttn : 0);
        reduce_kernel<<<BB, 384>>>(Wq, bq, Wk, bk, Wv, bv, gs, bs,
                                   Wih, bih, Whh, bhh, W1, b1, W2, b2, gm, bm,
                                   outSlots, last ? writeSlots : 0, !last);
    }
}